// round 17
// baseline (speedup 1.0000x reference)
#include <cuda_runtime.h>

// RoiPoolingConv: ROI-Align bilinear pooling, POOL=7
// img:  (8, 64, 64, 1024) float32, NHWC (channels contiguous)
// rois: (32, 4) int32  [x, y, w, h]
// out:  flat index ((r*8 + b)*7 + py)*7 + px, 1024 channels contiguous
//
// R17: R15 structure + 256-bit loads. ptxas revealed L2::evict_last only
// exists on .v4.b64/.v8.b32 (LDG.E.256) forms on sm_103a. Each thread owns
// 8 contiguous floats (32B): 4x 256-bit evict_last loads per tile (halves
// L1/L2 load-request count vs 8x16B — R13 showed request-volume cuts pay
// directly) + image lines biased to be retained in L2 across graph replays.
// Stores stay 2x __stcs float4 (no compile risk).

#define N_ROIS 32
#define N_BATCH 8
#define POOLP 7
#define CH 1024
#define CH4 (CH / 4)
#define IMG_W 64
#define IMG_H 64

struct F8 { float v[8]; };

__device__ __forceinline__ F8 ldg_el_256(const float* p)
{
    unsigned long long u0, u1, u2, u3;
    asm("ld.global.nc.L2::evict_last.v4.b64 {%0, %1, %2, %3}, [%4];"
        : "=l"(u0), "=l"(u1), "=l"(u2), "=l"(u3)
        : "l"(p));
    F8 r;
    r.v[0] = __uint_as_float((unsigned)u0);
    r.v[1] = __uint_as_float((unsigned)(u0 >> 32));
    r.v[2] = __uint_as_float((unsigned)u1);
    r.v[3] = __uint_as_float((unsigned)(u1 >> 32));
    r.v[4] = __uint_as_float((unsigned)u2);
    r.v[5] = __uint_as_float((unsigned)(u2 >> 32));
    r.v[6] = __uint_as_float((unsigned)u3);
    r.v[7] = __uint_as_float((unsigned)(u3 >> 32));
    return r;
}

__device__ __forceinline__ void st_out(float* p, const F8& r)
{
    float4 lo = make_float4(r.v[0], r.v[1], r.v[2], r.v[3]);
    float4 hi = make_float4(r.v[4], r.v[5], r.v[6], r.v[7]);
    __stcs((float4*)p, lo);
    __stcs((float4*)p + 1, hi);
}

__global__ void __launch_bounds__(128) roi_align_kernel_v17(
    const float* __restrict__ img,
    const int*   __restrict__ rois,
    float*       __restrict__ out)
{
    const int pypx = blockIdx.x;            // 0..48
    const int r    = blockIdx.y;            // 0..31
    const int b    = blockIdx.z;            // 0..7
    const int py   = pypx / POOLP;
    const int px   = pypx - py * POOLP;
    const int flat = (r * N_BATCH + b) * (POOLP * POOLP) + pypx;  // output tile

    const int rx = __ldg(&rois[r * 4 + 0]);
    const int ry = __ldg(&rois[r * 4 + 1]);
    const int rw = __ldg(&rois[r * 4 + 2]);
    const int rh = __ldg(&rois[r * 4 + 3]);

    const unsigned tc = threadIdx.x * 8u;   // this thread's first channel (0..1016)
    const unsigned base_b = (unsigned)b * (IMG_H * IMG_W * CH);   // float units
    float* const odst = out + (unsigned)flat * CH + tc;

    // Degenerate ROI (21x21): integer sample coords -> one corner load.
    if (((rw % POOLP) | (rh % POOLP)) == 0) {
        const int sx = rx + px * (rw / POOLP) + (rw / POOLP) / 2;
        const int sy = ry + py * (rh / POOLP) + (rh / POOLP) / 2;
        const F8 v = ldg_el_256(img + base_b + ((unsigned)sy * IMG_W + (unsigned)sx) * CH + tc);
        st_out(odst, v);
        return;
    }

    // coord = (p+0.5)*(size/POOL) - 0.5 (matches reference _edge)
    const float cx = ((float)px + 0.5f) * ((float)rw * (1.0f / POOLP)) - 0.5f;
    const float fx = floorf(cx);
    const int lox = max((int)fx, 0);
    const int hix = min(max((int)ceilf(cx), 0), rw - 1);
    const float wx = cx - fx;
    const int x0 = rx + lox;
    const int x1 = rx + hix;

    const float cy = ((float)py + 0.5f) * ((float)rh * (1.0f / POOLP)) - 0.5f;
    const float fy = floorf(cy);
    const int loy = max((int)fy, 0);
    const int hiy = min(max((int)ceilf(cy), 0), rh - 1);
    const float wy = cy - fy;
    const int y0 = ry + loy;
    const int y1 = ry + hiy;

    const float* pr0 = img + base_b + ((unsigned)y0 * IMG_W) * CH + tc;
    const float* pr1 = img + base_b + ((unsigned)y1 * IMG_W) * CH + tc;

    // 4 independent 256-bit loads, back-to-back
    const F8 a = ldg_el_256(pr0 + (unsigned)x0 * CH);
    const F8 bq = ldg_el_256(pr0 + (unsigned)x1 * CH);
    const F8 c = ldg_el_256(pr1 + (unsigned)x0 * CH);
    const F8 d = ldg_el_256(pr1 + (unsigned)x1 * CH);

    F8 res;
#pragma unroll
    for (int i = 0; i < 8; i++) {
        const float top = a.v[i] + (bq.v[i] - a.v[i]) * wx;
        const float bot = c.v[i] + (d.v[i] - c.v[i]) * wx;
        res.v[i] = top + (bot - top) * wy;
    }

    st_out(odst, res);
}

extern "C" void kernel_launch(void* const* d_in, const int* in_sizes, int n_in,
                              void* d_out, int out_size)
{
    const float* img  = (const float*)d_in[0];
    const int*   rois = (const int*)d_in[1];
    float*       out  = (float*)d_out;

    dim3 grid(POOLP * POOLP, N_ROIS, N_BATCH);   // x fastest -> batch outermost
    roi_align_kernel_v17<<<grid, 128>>>(img, rois, out);
}